// round 1
// baseline (speedup 1.0000x reference)
#include <cuda_runtime.h>
#include <math.h>

#define BATCH   64
#define NLIST   512
#define THREADS 512
#define JSPLIT  2
#define NBLK    (BATCH * JSPLIT)
#define JCHUNK  (NLIST / JSPLIT)

#define LOG_EPS (-23.025850929940457f)

__device__ float g_partial[NBLK];

__device__ __forceinline__ float f_inf() { return __int_as_float(0x7f800000); }

__global__ __launch_bounds__(THREADS)
void rank_loss_main(const float* __restrict__ logits,
                    const float* __restrict__ labels) {
    __shared__ float  s_sl[NLIST];     // masked logits (for ranking)
    __shared__ float4 sA[NLIST];       // {Gj, Ej, hj=gj/2, labj (+inf if invalid)}
    __shared__ float2 sB[NLIST];       // {qdj=0.25*disc_j, capped_j as int bits}
    __shared__ float  s_invlog[64];    // 1/log1p(k), k=1..51
    __shared__ float  s_rel75[64];     // 0.75*|1/log1p(rd) - 1/log1p(rd+1)|
    __shared__ float  s_wred[16];

    const int tid   = threadIdx.x;
    const int b     = blockIdx.x >> 1;
    const int jhalf = blockIdx.x & 1;

    // --- LUT setup (precise log1pf; setup-only cost) ---
    if (tid < 52) {
        s_invlog[tid] = (tid >= 1) ? (1.0f / log1pf((float)tid)) : 0.0f;
    }
    if (tid <= 50) {
        s_rel75[tid] = (tid == 0) ? 0.0f
            : 0.75f * fabsf(1.0f / log1pf((float)tid)
                          - 1.0f / log1pf((float)(tid + 1)));
    }

    // --- per-element load / masking ---
    const float g_raw   = logits[b * NLIST + tid];
    const float lab_raw = labels[b * NLIST + tid];
    const bool  valid   = lab_raw > -1000.0f;
    const float lab     = valid ? lab_raw : 0.0f;
    const float g       = valid ? g_raw : LOG_EPS;
    s_sl[tid] = g;
    __syncthreads();

    // --- rank: 1 + #{slj > sli} + #{slj == sli, j < i}  (== stable argsort) ---
    const float sli = g;
    int cnt = 0;
    const float4* sl4 = (const float4*)s_sl;
    #pragma unroll 4
    for (int j4 = 0; j4 < NLIST / 4; ++j4) {
        float4 v = sl4[j4];
        int j = 4 * j4;
        cnt += (v.x > sli) || ((v.x == sli) && (j + 0 < tid));
        cnt += (v.y > sli) || ((v.y == sli) && (j + 1 < tid));
        cnt += (v.z > sli) || ((v.z == sli) && (j + 2 < tid));
        cnt += (v.w > sli) || ((v.w == sli) && (j + 3 < tid));
    }
    const int   rank   = cnt + 1;
    const int   capped = min(rank, 51);
    const float disc   = (rank <= 50) ? s_invlog[rank] : 0.0f;

    // --- per-element precompute for pairwise phase ---
    const float Gi   = __expf(0.5f * g);    // exp(logit/2)
    const float Ei   = __expf(0.5f * lab);  // exp(label/2)
    const float hgi  = 0.5f * g;
    const float qdi  = 0.25f * disc;
    const float labi = valid ? lab : -f_inf();   // never wins the > compare

    sA[tid] = make_float4(Gi, Ei, hgi, valid ? lab : f_inf());
    sB[tid] = make_float2(qdi, __int_as_float(capped));
    __syncthreads();

    // --- per-row IDCG normalizer (thread 0 only; uses first 50 positions) ---
    float idcg = 0.0f;
    if (tid == 0) {
        float s = 0.0f;
        #pragma unroll
        for (int p = 1; p <= 50; ++p) {
            if (sA[p - 1].w < 1e30f) s += s_invlog[p];   // valid flag via sentinel
        }
        idcg = (s > 0.0f) ? (1.0f / s) : 0.0f;
    }

    // --- pairwise loop over this block's j-half ---
    const int j0 = jhalf * JCHUNK;
    float acc0 = 0.0f, acc1 = 0.0f;
    #pragma unroll 8
    for (int jj = 0; jj < JCHUNK; ++jj) {
        const int    j  = j0 + jj;
        const float4 A  = sA[j];
        const float2 Bv = sB[j];
        // target = Ei / (Ei + Ej)
        const float t  = __fdividef(Ei, Ei + A.y);
        // softplus((gi-gj)/2) = log(Gi+Gj) - gj/2
        const float sp = __logf(Gi + A.x) - A.z;
        const float x  = hgi - A.z;
        const float bce = fmaf(-t, x, sp);               // softplus(x) - t*x
        const int   rd  = abs(capped - __float_as_int(Bv.y));
        float w = s_rel75[rd] + fabsf(qdi - Bv.x);       // 0.75*rel + 0.25*|di-dj|
        w = (labi > A.w) ? w : 0.0f;                     // mask (branch-free)
        if (jj & 1) acc1 = fmaf(bce, w, acc1);
        else        acc0 = fmaf(bce, w, acc0);
    }
    float acc = acc0 + acc1;

    // --- deterministic block reduce ---
    #pragma unroll
    for (int o = 16; o; o >>= 1) acc += __shfl_down_sync(0xffffffffu, acc, o);
    if ((tid & 31) == 0) s_wred[tid >> 5] = acc;
    __syncthreads();
    if (tid < 16) {
        float v = s_wred[tid];
        #pragma unroll
        for (int o = 8; o; o >>= 1) v += __shfl_down_sync(0xffffu, v, o);
        if (tid == 0)
            g_partial[blockIdx.x] = v * idcg * (1.0f / (float)BATCH);
    }
}

__global__ __launch_bounds__(NBLK)
void rank_loss_reduce(float* __restrict__ out) {
    const int tid = threadIdx.x;
    float v = g_partial[tid];
    #pragma unroll
    for (int o = 16; o; o >>= 1) v += __shfl_down_sync(0xffffffffu, v, o);
    __shared__ float s_w[NBLK / 32];
    if ((tid & 31) == 0) s_w[tid >> 5] = v;
    __syncthreads();
    if (tid == 0) {
        float t = 0.0f;
        #pragma unroll
        for (int w = 0; w < NBLK / 32; ++w) t += s_w[w];
        out[0] = t;
    }
}

extern "C" void kernel_launch(void* const* d_in, const int* in_sizes, int n_in,
                              void* d_out, int out_size) {
    const float* logits = (const float*)d_in[0];
    const float* labels = (const float*)d_in[1];
    float* out = (float*)d_out;
    (void)in_sizes; (void)n_in; (void)out_size;

    rank_loss_main<<<NBLK, THREADS>>>(logits, labels);
    rank_loss_reduce<<<1, NBLK>>>(out);
}

// round 2
// speedup vs baseline: 1.0685x; 1.0685x over previous
#include <cuda_runtime.h>
#include <math.h>

#define BATCH   64
#define NLIST   512
#define THREADS 512
#define JSPLIT  2
#define NBLK    (BATCH * JSPLIT)
#define JCHUNK  (NLIST / JSPLIT)

#define LOG_EPS (-23.025850929940457f)
#define LN2F    0.6931471805599453f

__device__ float        g_partial[NBLK];
__device__ unsigned int g_count = 0;

__global__ __launch_bounds__(THREADS)
void rank_loss_main(const float* __restrict__ logits,
                    const float* __restrict__ labels,
                    float* __restrict__ out) {
    __shared__ unsigned long long s_key[NLIST];  // (mono_logit<<32) | (511-tid)
    __shared__ float4 sA[NLIST];                 // {Gj, Ej, hj, labj(+inf invalid)}
    __shared__ float2 sB[NLIST];                 // {0.25*disc_j, capped_j bits}
    __shared__ float  s_invlog[52];              // 1/log1p(k)
    __shared__ float  s_rel[52 * 32];            // replicated per-bank: [rd*32+lane]
    __shared__ float  s_red[16];
    __shared__ bool   s_last;

    const int tid   = threadIdx.x;
    const int lane  = tid & 31;
    const int b     = blockIdx.x >> 1;
    const int jhalf = blockIdx.x & 1;

    // --- LUT setup (setup-only cost; precise log1pf) ---
    if (tid < 52) s_invlog[tid] = tid ? (1.0f / log1pf((float)tid)) : 0.0f;
    for (int idx = tid; idx < 52 * 32; idx += THREADS) {
        int rd = idx >> 5;
        s_rel[idx] = rd ? 0.75f * fabsf(1.0f / log1pf((float)rd)
                                      - 1.0f / log1pf((float)(rd + 1)))
                        : 0.0f;
    }

    // --- per-element load / masking ---
    const float g_raw   = logits[b * NLIST + tid];
    const float lab_raw = labels[b * NLIST + tid];
    const bool  valid   = lab_raw > -1000.0f;
    const float lab     = valid ? lab_raw : 0.0f;
    const float g       = valid ? g_raw : LOG_EPS;

    // monotonic uint key: order(m) == order(g); tid tiebreak (smaller tid wins)
    const unsigned int ub = __float_as_uint(g);
    const unsigned int m  = ub ^ ((unsigned)((int)ub >> 31) | 0x80000000u);
    const unsigned long long ki =
        ((unsigned long long)m << 32) | (unsigned)(NLIST - 1 - tid);
    s_key[tid] = ki;
    __syncthreads();

    // --- rank = 1 + #{kj > ki}  (== stable argsort by descending logit) ---
    int cnt = 0;
    const ulonglong2* k2 = (const ulonglong2*)s_key;
    #pragma unroll 8
    for (int j2 = 0; j2 < NLIST / 2; ++j2) {
        ulonglong2 kk = k2[j2];
        cnt += (kk.x > ki);
        cnt += (kk.y > ki);
    }
    const int   rank   = cnt + 1;
    const int   capped = min(rank, 51);
    const float disc   = (rank <= 50) ? s_invlog[rank] : 0.0f;

    // --- per-element precompute ---
    const float Gi   = __expf(0.5f * g);     // exp(logit/2)
    const float Ei   = __expf(0.5f * lab);   // exp(label/2)
    const float hgi  = 0.5f * g;
    const float qdi  = 0.25f * disc;
    const float inf  = __int_as_float(0x7f800000);
    const float labi = valid ? lab : -inf;   // invalid i never wins '>'

    sA[tid] = make_float4(Gi, Ei, hgi, valid ? lab : inf);
    sB[tid] = make_float2(qdi, __int_as_float(capped));
    __syncthreads();

    // --- per-row IDCG (thread 0; only first 50 positions can contribute) ---
    float idcg = 0.0f;
    if (tid == 0) {
        float s = 0.0f;
        #pragma unroll
        for (int p = 1; p <= 50; ++p)
            if (sA[p - 1].w < 1e30f) s += s_invlog[p];
        idcg = (s > 0.0f) ? (1.0f / s) : 0.0f;
    }

    // --- pairwise loop over this block's j-half ---
    const float* relbase = s_rel + lane;     // [cd*32 + lane] -> bank == lane
    const int    j0      = jhalf * JCHUNK;
    float acc0 = 0.0f, acc1 = 0.0f;
    #pragma unroll 8
    for (int jj = 0; jj < JCHUNK; ++jj) {
        const int    j  = j0 + jj;
        const float4 A  = sA[j];             // broadcast LDS (N=1)
        const float2 Bv = sB[j];             // broadcast LDS (N=1)
        const float  t  = __fdividef(Ei, Ei + A.y);       // sigmoid(dlab/2)
        const float  lg = __log2f(Gi + A.x);              // lg2(e^hi + e^hj)
        const float  x  = hgi - A.z;
        const float  u2 = fmaf(-t, x, -A.z);              // -hj - t*x
        const float  bce = fmaf(lg, LN2F, u2);            // softplus(x) - t*x
        const int    cd  = abs(capped - __float_as_int(Bv.y));
        float w = relbase[cd << 5] + fabsf(qdi - Bv.x);   // conflict-free gather
        w = (labi > A.w) ? w : 0.0f;                      // pair mask
        if (jj & 1) acc1 = fmaf(bce, w, acc1);
        else        acc0 = fmaf(bce, w, acc0);
    }
    float acc = acc0 + acc1;

    // --- deterministic block reduce + partial write ---
    #pragma unroll
    for (int o = 16; o; o >>= 1) acc += __shfl_down_sync(0xffffffffu, acc, o);
    if (lane == 0) s_red[tid >> 5] = acc;
    __syncthreads();
    if (tid < 16) {
        float v = s_red[tid];
        #pragma unroll
        for (int o = 8; o; o >>= 1) v += __shfl_down_sync(0xffffu, v, o);
        if (tid == 0) {
            g_partial[blockIdx.x] = v * idcg * (1.0f / (float)BATCH);
            __threadfence();
            unsigned int old = atomicInc(&g_count, NBLK - 1); // wraps to 0
            s_last = (old == NBLK - 1);
        }
    }
    __syncthreads();

    // --- last block: deterministic final reduce, fused (no 2nd launch) ---
    if (s_last) {
        __threadfence();
        if (tid < NBLK) {
            float v = ((volatile float*)g_partial)[tid];
            #pragma unroll
            for (int o = 16; o; o >>= 1) v += __shfl_down_sync(0xffffffffu, v, o);
            if (lane == 0) s_red[tid >> 5] = v;
        }
        __syncthreads();
        if (tid == 0) {
            float tot = 0.0f;
            #pragma unroll
            for (int w2 = 0; w2 < NBLK / 32; ++w2) tot += s_red[w2];
            out[0] = tot;
        }
    }
}

extern "C" void kernel_launch(void* const* d_in, const int* in_sizes, int n_in,
                              void* d_out, int out_size) {
    const float* logits = (const float*)d_in[0];
    const float* labels = (const float*)d_in[1];
    float* out = (float*)d_out;
    (void)in_sizes; (void)n_in; (void)out_size;

    rank_loss_main<<<NBLK, THREADS>>>(logits, labels, out);
}

// round 3
// speedup vs baseline: 1.3653x; 1.2778x over previous
#include <cuda_runtime.h>
#include <math.h>

#define BATCH   64
#define NLIST   512
#define THREADS 512
#define NBLK    128            // 2 blocks per row (offset-split)

#define LOG_EPS (-23.025850929940457f)
#define LN2F    0.6931471805599453f

__device__ float        g_partial[NBLK];
__device__ unsigned int g_count = 0;

__global__ __launch_bounds__(THREADS)
void rank_loss_main(const float* __restrict__ logits,
                    const float* __restrict__ labels,
                    float* __restrict__ out) {
    __shared__ float  s_sl[NLIST];          // masked logits (rank phase, broadcast reads)
    __shared__ float4 sA[NLIST + 256];      // {Gj, Ej, hj, labj(NaN if invalid)} + mirror
    __shared__ float  sBp[NLIST + 256];     // qd with capped packed in low 8 mantissa bits
    __shared__ float  s_invlog[52];
    __shared__ float  s_rel[52 * 32];       // replicated: [cd*32 + lane] -> conflict-free
    __shared__ float  s_red[16];
    __shared__ bool   s_last;

    const int tid   = threadIdx.x;
    const int lane  = tid & 31;
    const int b     = blockIdx.x >> 1;
    const int jhalf = blockIdx.x & 1;

    // --- LUT setup ---
    if (tid < 52) s_invlog[tid] = tid ? (1.0f / log1pf((float)tid)) : 0.0f;
    for (int idx = tid; idx < 52 * 32; idx += THREADS) {
        int rd = idx >> 5;
        s_rel[idx] = rd ? 0.75f * fabsf(1.0f / log1pf((float)rd)
                                      - 1.0f / log1pf((float)(rd + 1)))
                        : 0.0f;
    }

    // --- per-element load / masking ---
    const float g_raw   = logits[b * NLIST + tid];
    const float lab_raw = labels[b * NLIST + tid];
    const bool  valid   = lab_raw > -1000.0f;
    const float lab     = valid ? lab_raw : 0.0f;
    const float g       = valid ? g_raw : LOG_EPS;
    s_sl[tid] = g;
    __syncthreads();

    // --- rank = 1 + #{slj > sli}; ties only among invalid cluster (capped=51, disc=0 either way,
    //     and invalid elements appear only in masked pairs) -> plain float compare is exact here ---
    int cnt = 0;
    const float4* sl4 = (const float4*)s_sl;
    #pragma unroll 8
    for (int j4 = 0; j4 < NLIST / 4; ++j4) {
        float4 v = sl4[j4];
        cnt += (v.x > g);
        cnt += (v.y > g);
        cnt += (v.z > g);
        cnt += (v.w > g);
    }
    const int   rank   = cnt + 1;
    const int   capped = min(rank, 51);
    const float disc   = (rank <= 50) ? s_invlog[rank] : 0.0f;

    // --- per-element precompute ---
    const float Gi   = __expf(0.5f * g);     // exp(logit/2)
    const float Ei   = __expf(0.5f * lab);   // exp(label/2)
    const float hi   = 0.5f * g;
    const float qdi  = 0.25f * disc;
    const float qnan = __int_as_float(0x7fffffff);
    const float labi = valid ? lab : qnan;   // NaN: all compares false -> pair inactive

    // pack capped into low 8 mantissa bits of qd (error < 2^-15 rel; qd=0 -> denormal ~1e-43)
    const unsigned qbits = (__float_as_uint(qdi) & ~0xFFu) | (unsigned)capped;
    const float4 Av = make_float4(Gi, Ei, hi, labi);
    sA[tid]  = Av;
    sBp[tid] = __uint_as_float(qbits);
    if (tid < 256) { sA[NLIST + tid] = Av; sBp[NLIST + tid] = __uint_as_float(qbits); }
    __syncthreads();

    // --- per-row IDCG (thread 0; first 50 positions, validity via NaN sentinel) ---
    float idcg = 0.0f;
    if (tid == 0) {
        float s = 0.0f;
        #pragma unroll
        for (int p = 1; p <= 50; ++p)
            if (sA[p - 1].w < 1e30f) s += s_invlog[p];   // NaN -> false
        idcg = (s > 0.0f) ? (1.0f / s) : 0.0f;
    }

    // --- unordered-pair loop: offsets o0..o0+127; each unordered pair visited exactly once
    //     (offset 256 double-covered -> gate to tid<256) ---
    const float* relbase = s_rel + lane;
    const int    o0      = 1 + (jhalf << 7);
    const float4* pA = sA  + tid + o0;
    const float*  pB = sBp + tid + o0;

    float acc = 0.0f;
    #pragma unroll 8
    for (int oo = 0; oo < 127; ++oo) {
        const float4 A  = pA[oo];
        const float  Bp = pB[oo];
        const bool p      = labi > A.w;                 // i is the bigger label
        const bool active = p || (A.w > labi);
        const float u   = p ? Ei : -A.y;
        const float ur  = __fdividef(u, Ei + A.y);      // ±E_big / (Ei+Ej)
        const float lg  = __log2f(Gi + A.x);
        const float dh  = hi - A.z;
        const float hs  = p ? A.z : hi;
        const float core = fmaf(lg, LN2F, -hs);
        const float bce  = fmaf(-dh, ur, core);         // softplus(x_big) - t*x_big
        const int   cj   = (int)(__float_as_uint(Bp) & 0xFFu);
        const int   cd   = abs(capped - cj);
        float w = relbase[cd << 5] + fabsf(qdi - Bp);
        w = active ? w : 0.0f;
        acc = fmaf(bce, w, acc);
    }
    {   // final offset (o0+127 == 128 or 256); offset 256 counted by both ends -> gate
        const float4 A  = pA[127];
        const float  Bp = pB[127];
        const bool gate   = (jhalf == 0) | (tid < 256);
        const bool p      = labi > A.w;
        const bool active = (p || (A.w > labi)) && gate;
        const float u   = p ? Ei : -A.y;
        const float ur  = __fdividef(u, Ei + A.y);
        const float lg  = __log2f(Gi + A.x);
        const float dh  = hi - A.z;
        const float hs  = p ? A.z : hi;
        const float core = fmaf(lg, LN2F, -hs);
        const float bce  = fmaf(-dh, ur, core);
        const int   cj   = (int)(__float_as_uint(Bp) & 0xFFu);
        const int   cd   = abs(capped - cj);
        float w = relbase[cd << 5] + fabsf(qdi - Bp);
        w = active ? w : 0.0f;
        acc = fmaf(bce, w, acc);
    }

    // --- deterministic block reduce + fused final reduce ---
    #pragma unroll
    for (int o = 16; o; o >>= 1) acc += __shfl_down_sync(0xffffffffu, acc, o);
    if (lane == 0) s_red[tid >> 5] = acc;
    __syncthreads();
    if (tid < 16) {
        float v = s_red[tid];
        #pragma unroll
        for (int o = 8; o; o >>= 1) v += __shfl_down_sync(0xffffu, v, o);
        if (tid == 0) {
            g_partial[blockIdx.x] = v * idcg * (1.0f / (float)BATCH);
            __threadfence();
            unsigned int old = atomicInc(&g_count, NBLK - 1);  // wraps -> replay-safe
            s_last = (old == NBLK - 1);
        }
    }
    __syncthreads();

    if (s_last) {
        __threadfence();
        if (tid < NBLK) {
            float v = ((volatile float*)g_partial)[tid];
            #pragma unroll
            for (int o = 16; o; o >>= 1) v += __shfl_down_sync(0xffffffffu, v, o);
            if (lane == 0) s_red[tid >> 5] = v;
        }
        __syncthreads();
        if (tid == 0) {
            float tot = 0.0f;
            #pragma unroll
            for (int w2 = 0; w2 < NBLK / 32; ++w2) tot += s_red[w2];
            out[0] = tot;
        }
    }
}

extern "C" void kernel_launch(void* const* d_in, const int* in_sizes, int n_in,
                              void* d_out, int out_size) {
    const float* logits = (const float*)d_in[0];
    const float* labels = (const float*)d_in[1];
    float* out = (float*)d_out;
    (void)in_sizes; (void)n_in; (void)out_size;

    rank_loss_main<<<NBLK, THREADS>>>(logits, labels, out);
}